// round 4
// baseline (speedup 1.0000x reference)
#include <cuda_runtime.h>
#include <math.h>

#define CIN 64
#define COUT_PER 32
#define LALPHA 0.2f

// ---------------- static device scratch ----------------
// D (forward DFT [r][t]) and C (inverse DFT [t][j]) tables, packed per fft:
//   off: fft32 -> 0, fft64 -> 1088, fft128 -> 5312
__device__ float g_D[21952];
__device__ float g_C[21952];
// Combined per-bin weights G[k][j=ri*64+c][o2=2o+rio], 128x64 per bin
//   off: fft32 -> 0, fft64 -> 139264, fft128 -> 409600
__device__ float g_G[942080];
// X[k][f][ri][c]: offs 0, 4456448, 8781824
__device__ float g_X[13041664];
// Z[f][j=2k+ri][o] (j stride 32): offs 0, 2228224, 4390912
__device__ float g_Z[6520832];

__device__ __forceinline__ float lk(float v) { return v > 0.f ? v : LALPHA * v; }

// ---------------- precompute: DFT / iDFT tables ----------------
__global__ void k_build_dft() {
    int ffti = blockIdx.y;
    int N = 32 << ffti;
    int bins = N / 2 + 1;
    int R = 2 * bins;
    int total = R * N;
    int off = (ffti == 0) ? 0 : (ffti == 1 ? 1088 : 5312);
    int stride = gridDim.x * blockDim.x;
    for (int idx = blockIdx.x * blockDim.x + threadIdx.x; idx < total; idx += stride) {
        {   // D [r][t]
            int r = idx / N, t = idx % N;
            int k = r >> 1, ri = r & 1;
            int m = (k * t) % N;
            float s, c;
            sincospif(2.0f * (float)m / (float)N, &s, &c);
            g_D[off + idx] = ri ? -s : c;
        }
        {   // C [t][j]
            int t = idx / R, j = idx % R;
            int k = j >> 1, ri = j & 1;
            int m = (k * t) % N;
            float s, c;
            sincospif(2.0f * (float)m / (float)N, &s, &c);
            float w = (k == 0 || k == bins - 1) ? 1.0f : 2.0f;
            g_C[off + idx] = (ri ? -s : c) * (w / (float)N);
        }
    }
}

// ---------------- precompute: resized kernels -> G ----------------
__global__ void k_build_G(const float* __restrict__ kr, const float* __restrict__ ki) {
    int ffti = blockIdx.y;
    int N = 32 << ffti;
    int bins = N / 2 + 1;
    int goff = (ffti == 0) ? 0 : (ffti == 1 ? 139264 : 409600);
    int total = bins * CIN * COUT_PER;
    int stride = gridDim.x * blockDim.x;
    for (int idx = blockIdx.x * blockDim.x + threadIdx.x; idx < total; idx += stride) {
        int k = idx / (CIN * COUT_PER);
        int rem = idx % (CIN * COUT_PER);
        int c = rem / COUT_PER, o = rem % COUT_PER;
        float vr, vi;
        if (bins == 33) {
            vr = kr[k * 2048 + rem];
            vi = ki[k * 2048 + rem];
        } else {
            float src = (k + 0.5f) * (33.0f / (float)bins) - 0.5f;
            float fl = floorf(src);
            int i0 = (int)fl;
            float f = src - fl;
            int i0c = i0 < 0 ? 0 : i0;
            int i1c = i0 + 1 > 32 ? 32 : i0 + 1;
            vr = (1.0f - f) * kr[i0c * 2048 + rem] + f * kr[i1c * 2048 + rem];
            vi = (1.0f - f) * ki[i0c * 2048 + rem] + f * ki[i1c * 2048 + rem];
        }
        float* Gk = g_G + goff + k * 8192;
        Gk[c * 64 + 2 * o]            = vr;
        Gk[c * 64 + 2 * o + 1]        = vi;
        Gk[(64 + c) * 64 + 2 * o]     = -vi;
        Gk[(64 + c) * 64 + 2 * o + 1] = vr;
    }
}

// ---------------- stage 1: forward DFT ----------------
// Rows 1 and N+1 of D are identically zero (Im at k=0, k=N/2) -> compute N rows
// (remapped 0,2,3,...,N), write the two zero rows directly.
template <int N, int FR, int DOFF, int XOFF, int F>
__global__ void k_stage1(const float* __restrict__ x) {
    constexpr int RT = N / 32;           // rows per thread
    extern __shared__ float sm[];
    float* D_s = sm;                     // N x (N+1), remapped rows
    float* x_s = sm + N * (N + 1);       // FR x N x 64
    const int tid = threadIdx.x;
    const int f0 = blockIdx.x * FR;

    for (int idx = tid; idx < N * N; idx += 256) {
        int rp = idx / N, t = idx % N;
        int ra = rp + (rp > 0);
        D_s[rp * (N + 1) + t] = g_D[DOFF + ra * N + t];
    }
    const float4* xg = reinterpret_cast<const float4*>(x + (size_t)f0 * N * 64);
    float4* xs4 = reinterpret_cast<float4*>(x_s);
    for (int idx = tid; idx < FR * N * 16; idx += 256) xs4[idx] = xg[idx];
    __syncthreads();

    const int tx = tid & 7;              // col octet (8 cols)
    const int ty = tid >> 3;             // 0..31, rows ty+32*i

    float acc[FR][RT][8];
#pragma unroll
    for (int fr = 0; fr < FR; fr++)
#pragma unroll
        for (int i = 0; i < RT; i++)
#pragma unroll
            for (int jj = 0; jj < 8; jj++) acc[fr][i][jj] = 0.f;

#pragma unroll 4
    for (int t = 0; t < N; t++) {
        float a[RT];
#pragma unroll
        for (int i = 0; i < RT; i++) a[i] = D_s[(ty + 32 * i) * (N + 1) + t];
#pragma unroll
        for (int fr = 0; fr < FR; fr++) {
            float4 b0 = xs4[(fr * N + t) * 16 + 2 * tx];
            float4 b1 = xs4[(fr * N + t) * 16 + 2 * tx + 1];
#pragma unroll
            for (int i = 0; i < RT; i++) {
                acc[fr][i][0] += a[i] * b0.x; acc[fr][i][1] += a[i] * b0.y;
                acc[fr][i][2] += a[i] * b0.z; acc[fr][i][3] += a[i] * b0.w;
                acc[fr][i][4] += a[i] * b1.x; acc[fr][i][5] += a[i] * b1.y;
                acc[fr][i][6] += a[i] * b1.z; acc[fr][i][7] += a[i] * b1.w;
            }
        }
    }

#pragma unroll
    for (int fr = 0; fr < FR; fr++)
#pragma unroll
        for (int i = 0; i < RT; i++) {
            int rp = ty + 32 * i;
            int ra = rp + (rp > 0);
            int k = ra >> 1, ri = ra & 1;
            float* dst = g_X + XOFF + ((size_t)(k * F + f0 + fr) * 2 + ri) * 64 + 8 * tx;
            *reinterpret_cast<float4*>(dst) =
                make_float4(acc[fr][i][0], acc[fr][i][1], acc[fr][i][2], acc[fr][i][3]);
            *reinterpret_cast<float4*>(dst + 4) =
                make_float4(acc[fr][i][4], acc[fr][i][5], acc[fr][i][6], acc[fr][i][7]);
        }

    // zero rows: (k=0, ri=1) and (k=N/2, ri=1)
    if (tid < FR * 32) {
        int fr = tid >> 5, m = tid & 31;
        int kz = (m >> 4) ? (N / 2) : 0;
        int q = m & 15;
        *reinterpret_cast<float4*>(
            g_X + XOFF + ((size_t)(kz * F + f0 + fr) * 2 + 1) * 64 + 4 * q) =
            make_float4(0.f, 0.f, 0.f, 0.f);
    }
}

// ---------------- stage 2: per-bin [128f x 128] x [128 x 64] + leaky ----------------
__global__ void k_stage2(int xoff, int goff, int zoff, int F, int bins) {
    extern __shared__ float sm[];
    float* A_s = sm;               // 128 rows, stride 132
    float* B_s = sm + 128 * 132;   // 128 x 64
    const int tid = threadIdx.x;
    const int k = blockIdx.y;
    const int f0 = blockIdx.x * 128;

    const float4* Xg = reinterpret_cast<const float4*>(g_X + xoff + ((size_t)k * F + f0) * 128);
    float4* A4 = reinterpret_cast<float4*>(A_s);
    for (int idx = tid; idx < 128 * 32; idx += 256)
        A4[(idx >> 5) * 33 + (idx & 31)] = Xg[idx];
    const float4* Gg = reinterpret_cast<const float4*>(g_G + goff + (size_t)k * 8192);
    float4* B4 = reinterpret_cast<float4*>(B_s);
    for (int idx = tid; idx < 2048; idx += 256) B4[idx] = Gg[idx];
    __syncthreads();

    const int tx = tid & 7;   // col octet
    const int ty = tid >> 3;  // rows ty + 32*i

    float acc[4][8];
#pragma unroll
    for (int i = 0; i < 4; i++)
#pragma unroll
        for (int jj = 0; jj < 8; jj++) acc[i][jj] = 0.f;

#pragma unroll 4
    for (int j = 0; j < 128; j++) {
        float4 b0 = *reinterpret_cast<const float4*>(B_s + j * 64 + 8 * tx);
        float4 b1 = *reinterpret_cast<const float4*>(B_s + j * 64 + 8 * tx + 4);
        float a[4];
#pragma unroll
        for (int i = 0; i < 4; i++) a[i] = A_s[(ty + 32 * i) * 132 + j];
#pragma unroll
        for (int i = 0; i < 4; i++) {
            acc[i][0] += a[i] * b0.x; acc[i][1] += a[i] * b0.y;
            acc[i][2] += a[i] * b0.z; acc[i][3] += a[i] * b0.w;
            acc[i][4] += a[i] * b1.x; acc[i][5] += a[i] * b1.y;
            acc[i][6] += a[i] * b1.z; acc[i][7] += a[i] * b1.w;
        }
    }

#pragma unroll
    for (int i = 0; i < 4; i++) {
        int f = f0 + ty + 32 * i;
        float* zp = g_Z + zoff + ((size_t)f * bins + k) * 64;
        // cols o2 = 8*tx + jj; even jj -> ri=0 (o=4tx+jj/2), odd jj -> ri=1
        *reinterpret_cast<float4*>(zp + 4 * tx) =
            make_float4(lk(acc[i][0]), lk(acc[i][2]), lk(acc[i][4]), lk(acc[i][6]));
        *reinterpret_cast<float4*>(zp + 32 + 4 * tx) =
            make_float4(lk(acc[i][1]), lk(acc[i][3]), lk(acc[i][5]), lk(acc[i][7]));
    }
}

// ---------------- stage 3: irfft + bias ----------------
// Columns 1 and N+1 of C are zero -> compact j-loop to N iterations.
template <int N, int GG, int COFF, int ZOFF, int OOFF>
__global__ void k_stage3(float* __restrict__ out, const float* __restrict__ bias) {
    constexpr int BINS = N / 2 + 1;
    constexpr int R = 2 * BINS;
    constexpr int FPC = 128 / N;          // frames per pass
    constexpr int TPF = 256 / FPC;        // threads per frame
    extern __shared__ float sm[];
    float* C_s = sm;                      // N x (N+1) compact
    float* Z_s = sm + N * (N + 1);        // FPC x (R*32)
    const int tid = threadIdx.x;

    for (int idx = tid; idx < N * N; idx += 256) {
        int t = idx / N, jj = idx % N;
        int ja = jj + (jj > 0);
        C_s[t * (N + 1) + jj] = g_C[COFF + t * R + ja];
    }
    const int fl = tid / TPF;
    const int tx = tid & 3;                    // col octet of 8 (32 cols)
    const int tyy = (tid >> 2) & (N / 2 - 1);  // row pair

    const float4 bv0 = *reinterpret_cast<const float4*>(bias + OOFF + 8 * tx);
    const float4 bv1 = *reinterpret_cast<const float4*>(bias + OOFF + 8 * tx + 4);

    for (int g = 0; g < GG; g++) {
        const int f0 = (blockIdx.x * GG + g) * FPC;
        __syncthreads();
        const float4* Zg = reinterpret_cast<const float4*>(g_Z + ZOFF + (size_t)f0 * BINS * 64);
        float4* Z4 = reinterpret_cast<float4*>(Z_s);
        for (int idx = tid; idx < FPC * BINS * 16; idx += 256) Z4[idx] = Zg[idx];
        __syncthreads();

        const float* Zf = Z_s + fl * (R * 32);
        float acc[2][8];
#pragma unroll
        for (int rr = 0; rr < 2; rr++)
#pragma unroll
            for (int jj = 0; jj < 8; jj++) acc[rr][jj] = 0.f;

#pragma unroll 4
        for (int j = 0; j < N; j++) {
            int ja = j + (j > 0);
            const float* Zj = Zf + ja * 32 + 8 * tx;
            float4 b0 = *reinterpret_cast<const float4*>(Zj);
            float4 b1 = *reinterpret_cast<const float4*>(Zj + 4);
            float a0 = C_s[(2 * tyy) * (N + 1) + j];
            float a1 = C_s[(2 * tyy + 1) * (N + 1) + j];
            acc[0][0] += a0 * b0.x; acc[0][1] += a0 * b0.y;
            acc[0][2] += a0 * b0.z; acc[0][3] += a0 * b0.w;
            acc[0][4] += a0 * b1.x; acc[0][5] += a0 * b1.y;
            acc[0][6] += a0 * b1.z; acc[0][7] += a0 * b1.w;
            acc[1][0] += a1 * b0.x; acc[1][1] += a1 * b0.y;
            acc[1][2] += a1 * b0.z; acc[1][3] += a1 * b0.w;
            acc[1][4] += a1 * b1.x; acc[1][5] += a1 * b1.y;
            acc[1][6] += a1 * b1.z; acc[1][7] += a1 * b1.w;
        }

        const int f = f0 + fl;
#pragma unroll
        for (int rr = 0; rr < 2; rr++) {
            int t = 2 * tyy + rr;
            float* op = out + ((size_t)f * N + t) * 96 + OOFF + 8 * tx;
            *reinterpret_cast<float4*>(op) = make_float4(
                acc[rr][0] + bv0.x, acc[rr][1] + bv0.y, acc[rr][2] + bv0.z, acc[rr][3] + bv0.w);
            *reinterpret_cast<float4*>(op + 4) = make_float4(
                acc[rr][4] + bv1.x, acc[rr][5] + bv1.y, acc[rr][6] + bv1.z, acc[rr][7] + bv1.w);
        }
    }
}

// ---------------- launch ----------------
extern "C" void kernel_launch(void* const* d_in, const int* in_sizes, int n_in,
                              void* d_out, int out_size) {
    const float* x    = (const float*)d_in[0];
    const float* kr   = (const float*)d_in[1];
    const float* ki   = (const float*)d_in[2];
    const float* bias = (const float*)d_in[3];
    float* out = (float*)d_out;

    const int s1_32  = (32 * 33 + 4 * 32 * 64) * 4;   // 36992
    const int s1_64  = (64 * 65 + 2 * 64 * 64) * 4;   // 49408
    const int s1_128 = (128 * 129 + 128 * 64) * 4;    // 98816
    const int s2     = (128 * 132 + 128 * 64) * 4;    // 100352
    const int s3_32  = (32 * 33 + 4 * 68 * 32) * 4;   // 39040
    const int s3_64  = (64 * 65 + 2 * 66 * 32) * 4;   // 33536
    const int s3_128 = (128 * 129 + 130 * 32) * 4;    // 82688

    cudaFuncSetAttribute(k_stage1<64, 2, 1088, 4456448, 1024>,
                         cudaFuncAttributeMaxDynamicSharedMemorySize, s1_64);
    cudaFuncSetAttribute(k_stage1<128, 1, 5312, 8781824, 512>,
                         cudaFuncAttributeMaxDynamicSharedMemorySize, s1_128);
    cudaFuncSetAttribute(k_stage2, cudaFuncAttributeMaxDynamicSharedMemorySize, s2);
    cudaFuncSetAttribute(k_stage3<128, 2, 5312, 4390912, 64>,
                         cudaFuncAttributeMaxDynamicSharedMemorySize, s3_128);

    k_build_dft<<<dim3(65, 3), 256>>>();
    k_build_G<<<dim3(520, 3), 256>>>(kr, ki);

    k_stage1<32, 4, 0, 0, 2048><<<512, 256, s1_32>>>(x);
    k_stage1<64, 2, 1088, 4456448, 1024><<<512, 256, s1_64>>>(x);
    k_stage1<128, 1, 5312, 8781824, 512><<<512, 256, s1_128>>>(x);

    k_stage2<<<dim3(16, 17), 256, s2>>>(0, 0, 0, 2048, 17);
    k_stage2<<<dim3(8, 33), 256, s2>>>(4456448, 139264, 2228224, 1024, 33);
    k_stage2<<<dim3(4, 65), 256, s2>>>(8781824, 409600, 4390912, 512, 65);

    k_stage3<32, 2, 0, 0, 0><<<256, 256, s3_32>>>(out, bias);
    k_stage3<64, 2, 1088, 2228224, 32><<<256, 256, s3_64>>>(out, bias);
    k_stage3<128, 2, 5312, 4390912, 64><<<256, 256, s3_128>>>(out, bias);
}